// round 11
// baseline (speedup 1.0000x reference)
#include <cuda_runtime.h>
#include <cuda_bf16.h>
#include <cstdint>

// ---------------------------------------------------------------------------
// GeneInteractionDango v10: 8 warps/block (n16 slices), 2 blocks/SM =
// 16 warps/SM for latency hiding; regs capped at 128 via launch_bounds.
// V*O algebraic fusion kept, but Wvo now hi/lo split (2 accumulated B
// streams over one A pass) to restore precision margin.
// B operands pre-packed as mma fragments in global (LDG from L2, no smem).
// ---------------------------------------------------------------------------

#define GROUPS   131072
#define SEQ      3
#define H        128
#define GPB      16
#define TPB      48
#define NTHREADS 256

#define XSTR     132      // f32 row stride (words)
#define RB       272u     // bf16 row stride bytes

// smem byte offsets
#define XS_OFF   0        // f32 [48][132] = 25344
#define AB_OFF   25344    // bf16 [48][136] = 13056
#define QB_OFF   38400
#define KB_OFF   51456
#define VB_OFF   64512
#define WP_OFF   77568    // f32[128]
#define BS_OFF   78080    // f32[128]
#define B_OFF    78592    // f32[512] biases {bq, bk, bvo, bo}
#define SC_OFF   80640    // f32[48]
#define SMEM_SZ  80832

typedef unsigned long long u64;

// frag images: per layer {0:Wq 1:Wk 2:Wvo_hi 3:Wvo_lo}; 8:Ws_hi 9:Ws_lo
// frag[((img*8 + ks)*16 + j)*32 + lane] = (b0 | b1<<32)
__device__ __align__(16) u64   g_frag[10 * 8 * 16 * 32];
__device__ __align__(16) float g_wvo[2][H * H];     // Wv@Wo, [k][n] fp32
__device__ __align__(16) float g_bvo[2][H];         // bv@Wo

__device__ __forceinline__ void mma_bf16(float* c,
                                         uint32_t a0, uint32_t a1, uint32_t a2, uint32_t a3,
                                         uint32_t b0, uint32_t b1)
{
    asm volatile(
        "mma.sync.aligned.m16n8k16.row.col.f32.bf16.bf16.f32 "
        "{%0,%1,%2,%3}, {%4,%5,%6,%7}, {%8,%9}, {%0,%1,%2,%3};"
        : "+f"(c[0]), "+f"(c[1]), "+f"(c[2]), "+f"(c[3])
        : "r"(a0), "r"(a1), "r"(a2), "r"(a3), "r"(b0), "r"(b1));
}

__device__ __forceinline__ void ldsm_x4(uint32_t& r0, uint32_t& r1, uint32_t& r2, uint32_t& r3,
                                        uint32_t addr)
{
    asm volatile("ldmatrix.sync.aligned.m8n8.x4.shared.b16 {%0,%1,%2,%3}, [%4];"
                 : "=r"(r0), "=r"(r1), "=r"(r2), "=r"(r3) : "r"(addr));
}

__device__ __forceinline__ uint32_t smem_u32(const void* p) {
    uint32_t a;
    asm("{ .reg .u64 t; cvta.to.shared.u64 t, %1; cvt.u32.u64 %0, t; }" : "=r"(a) : "l"(p));
    return a;
}

__device__ __forceinline__ uint32_t bf16x2(float a, float b) {
    __nv_bfloat162 v = __floats2bfloat162_rn(a, b);
    return *(uint32_t*)&v;
}

// [48x128] @ [128x16] slice: A via ldmatrix (3 m16 stripes), one B stream.
__device__ __forceinline__ void gemm3g(uint32_t aBase, uint32_t aoff,
                                       const u64* __restrict__ fb,
                                       float acc[3][2][4])
{
    u64 cur[2];
    cur[0] = __ldg(fb);
    cur[1] = __ldg(fb + 32);
#pragma unroll
    for (int ks = 0; ks < 8; ks++) {
        uint32_t a[3][4];
#pragma unroll
        for (int s = 0; s < 3; s++)
            ldsm_x4(a[s][0], a[s][1], a[s][2], a[s][3],
                    aBase + (uint32_t)s * (16u * RB) + aoff + (uint32_t)ks * 32u);
        u64 nxt[2];
        if (ks < 7) {
            nxt[0] = __ldg(fb + (ks + 1) * 512);
            nxt[1] = __ldg(fb + (ks + 1) * 512 + 32);
        }
#pragma unroll
        for (int s = 0; s < 3; s++)
#pragma unroll
            for (int j = 0; j < 2; j++)
                mma_bf16(acc[s][j], a[s][0], a[s][1], a[s][2], a[s][3],
                         (uint32_t)cur[j], (uint32_t)(cur[j] >> 32));
        if (ks < 7) { cur[0] = nxt[0]; cur[1] = nxt[1]; }
    }
}

// two B streams (hi+lo) accumulated into ONE acc over a single A pass
__device__ __forceinline__ void gemm3g_b2(uint32_t aBase, uint32_t aoff,
                                          const u64* __restrict__ fb1,
                                          const u64* __restrict__ fb2,
                                          float acc[3][2][4])
{
#pragma unroll
    for (int ks = 0; ks < 8; ks++) {
        u64 c1[2], c2[2];
        c1[0] = __ldg(fb1 + ks * 512);       c1[1] = __ldg(fb1 + ks * 512 + 32);
        c2[0] = __ldg(fb2 + ks * 512);       c2[1] = __ldg(fb2 + ks * 512 + 32);
        uint32_t a[3][4];
#pragma unroll
        for (int s = 0; s < 3; s++)
            ldsm_x4(a[s][0], a[s][1], a[s][2], a[s][3],
                    aBase + (uint32_t)s * (16u * RB) + aoff + (uint32_t)ks * 32u);
#pragma unroll
        for (int s = 0; s < 3; s++)
#pragma unroll
            for (int j = 0; j < 2; j++) {
                mma_bf16(acc[s][j], a[s][0], a[s][1], a[s][2], a[s][3],
                         (uint32_t)c1[j], (uint32_t)(c1[j] >> 32));
                mma_bf16(acc[s][j], a[s][0], a[s][1], a[s][2], a[s][3],
                         (uint32_t)c2[j], (uint32_t)(c2[j] >> 32));
            }
    }
}

// dual-A, shared-B (static hi*hi + lo*hi)
__device__ __forceinline__ void gemm3g_dual(uint32_t aBase1, uint32_t aBase2, uint32_t aoff,
                                            const u64* __restrict__ fb,
                                            float acc[3][2][4])
{
#pragma unroll
    for (int ks = 0; ks < 8; ks++) {
        u64 cur[2];
        cur[0] = __ldg(fb + ks * 512);
        cur[1] = __ldg(fb + ks * 512 + 32);
        uint32_t a1[3][4], a2[3][4];
#pragma unroll
        for (int s = 0; s < 3; s++) {
            ldsm_x4(a1[s][0], a1[s][1], a1[s][2], a1[s][3],
                    aBase1 + (uint32_t)s * (16u * RB) + aoff + (uint32_t)ks * 32u);
            ldsm_x4(a2[s][0], a2[s][1], a2[s][2], a2[s][3],
                    aBase2 + (uint32_t)s * (16u * RB) + aoff + (uint32_t)ks * 32u);
        }
#pragma unroll
        for (int s = 0; s < 3; s++)
#pragma unroll
            for (int j = 0; j < 2; j++) {
                uint32_t b0 = (uint32_t)cur[j], b1 = (uint32_t)(cur[j] >> 32);
                mma_bf16(acc[s][j], a1[s][0], a1[s][1], a1[s][2], a1[s][3], b0, b1);
                mma_bf16(acc[s][j], a2[s][0], a2[s][1], a2[s][2], a2[s][3], b0, b1);
            }
    }
}

__device__ __forceinline__ void zero_acc(float acc[3][2][4]) {
#pragma unroll
    for (int s = 0; s < 3; s++)
#pragma unroll
        for (int j = 0; j < 2; j++)
#pragma unroll
            for (int e = 0; e < 4; e++) acc[s][j][e] = 0.f;
}

__device__ __forceinline__ void build_A(const float* __restrict__ Xs,
                                        unsigned char* __restrict__ smA, int tid)
{
#pragma unroll
    for (int i = 0; i < 12; i++) {
        int p = tid + i * NTHREADS;          // 3072 pairs
        int row = p >> 6, cp = p & 63;
        float2 v = *(const float2*)(Xs + row * XSTR + 2 * cp);
        *(uint32_t*)(smA + (uint32_t)row * RB + (uint32_t)cp * 4u) = bf16x2(v.x, v.y);
    }
}

__device__ __forceinline__ void epi_qkv(const float acc[3][2][4], const float* __restrict__ bias,
                                        unsigned char* __restrict__ dst, int n0, int g, int tg)
{
#pragma unroll
    for (int s = 0; s < 3; s++) {
        int r0 = 16 * s + g;
#pragma unroll
        for (int j = 0; j < 2; j++) {
            int c = n0 + 8 * j + 2 * tg;
            float bv0 = bias[c], bv1 = bias[c + 1];
            *(uint32_t*)(dst + (uint32_t)r0 * RB + 2u * c) =
                bf16x2(acc[s][j][0] + bv0, acc[s][j][1] + bv1);
            *(uint32_t*)(dst + (uint32_t)(r0 + 8) * RB + 2u * c) =
                bf16x2(acc[s][j][2] + bv0, acc[s][j][3] + bv1);
        }
    }
}

// ---------------------------------------------------------------------------
// prep 1: Wvo = Wv@Wo (fp32), bvo = bv@Wo
// ---------------------------------------------------------------------------
__global__ void dango_prep_vo(const float* __restrict__ Wv, const float* __restrict__ Wo,
                              const float* __restrict__ bv)
{
    int b = blockIdx.x;
    int n = threadIdx.x;
    if (b < 256) {
        int l = b >> 7, k = b & 127;
        const float* wv = Wv + (size_t)l * H * H + (size_t)k * H;
        const float* wo = Wo + (size_t)l * H * H;
        float s = 0.f;
#pragma unroll 8
        for (int m = 0; m < H; m++) s += __ldg(wv + m) * __ldg(wo + m * H + n);
        g_wvo[l][k * H + n] = s;
    } else {
        int l = b - 256;
        const float* wo = Wo + (size_t)l * H * H;
        const float* bvp = bv + l * H;
        float s = 0.f;
#pragma unroll 8
        for (int k = 0; k < H; k++) s += __ldg(bvp + k) * __ldg(wo + k * H + n);
        g_bvo[l][n] = s;
    }
}

// ---------------------------------------------------------------------------
// prep 2: pack 10 weight images into mma-fragment order.
// images: l*4+{0:Wq 1:Wk 2:Wvo_hi 3:Wvo_lo}; 8:Ws_hi 9:Ws_lo
// (img, ks, j, lane): n = 8j + (lane>>2), k0 = 16ks + 2(lane&3)
// ---------------------------------------------------------------------------
__global__ void dango_prep_pack(const float* __restrict__ Ws,
                                const float* __restrict__ Wq, const float* __restrict__ Wk)
{
    int t = blockIdx.x * 256 + threadIdx.x;      // 0..40959
    int img  = t >> 12;
    int r    = t & 4095;
    int ks   = r >> 9;
    int j    = (r >> 5) & 15;
    int lane = r & 31;
    int n  = 8 * j + (lane >> 2);
    int k0 = 16 * ks + 2 * (lane & 3);

    const float* src;
    int lo = 0;
    if (img < 8) {
        int l = img >> 2, m = img & 3;
        if      (m == 0) src = Wq + (size_t)l * H * H;
        else if (m == 1) src = Wk + (size_t)l * H * H;
        else { src = g_wvo[l]; lo = (m == 3); }
    } else {
        src = Ws;
        lo = (img == 9);
    }

    float w[4];
    w[0] = __ldg(src + (k0)     * H + n);
    w[1] = __ldg(src + (k0 + 1) * H + n);
    w[2] = __ldg(src + (k0 + 8) * H + n);
    w[3] = __ldg(src + (k0 + 9) * H + n);

    __nv_bfloat16 v[4];
#pragma unroll
    for (int i = 0; i < 4; i++) {
        if (!lo) v[i] = __float2bfloat16(w[i]);
        else {
            __nv_bfloat16 h = __float2bfloat16(w[i]);
            v[i] = __float2bfloat16(w[i] - __bfloat162float(h));
        }
    }
    uint32_t b0, b1;
    { __nv_bfloat162 p = __halves2bfloat162(v[0], v[1]); b0 = *(uint32_t*)&p; }
    { __nv_bfloat162 p = __halves2bfloat162(v[2], v[3]); b1 = *(uint32_t*)&p; }
    g_frag[t] = (u64)b0 | ((u64)b1 << 32);
}

__global__ __launch_bounds__(NTHREADS, 2)
void dango_mma(const float* __restrict__ X0,
               const float* __restrict__ bs_, const float* __restrict__ bq_,
               const float* __restrict__ bk_, const float* __restrict__ bo_,
               const float* __restrict__ beta,
               const float* __restrict__ Wp, const float* __restrict__ bp,
               float* __restrict__ out)
{
    extern __shared__ unsigned char sm[];
    float*         Xs = (float*)(sm + XS_OFF);
    unsigned char* Ab = sm + AB_OFF;
    unsigned char* Qb = sm + QB_OFF;
    unsigned char* Kb = sm + KB_OFF;
    unsigned char* Vb = sm + VB_OFF;
    float* sWp = (float*)(sm + WP_OFF);
    float* sBs = (float*)(sm + BS_OFF);
    float* sB  = (float*)(sm + B_OFF);
    float* sSc = (float*)(sm + SC_OFF);

    const int tid  = threadIdx.x;
    const int wid  = tid >> 5;
    const int lane = tid & 31;
    const int g    = lane >> 2;
    const int tg   = lane & 3;
    const int n0   = wid * 16;              // n-slice per warp (8 warps)
    const int g0   = blockIdx.x * GPB;
    const size_t base = (size_t)g0 * SEQ * H;

    const uint32_t smbase = smem_u32(sm);
    const uint32_t aoff   = (uint32_t)(lane & 15) * RB + (uint32_t)(lane >> 4) * 16u;
    const uint32_t AbA = smbase + AB_OFF;
    const uint32_t KbA = smbase + KB_OFF, VbA = smbase + VB_OFF;
    const u64* fwarp = g_frag + wid * 64 + lane;   // + img*4096 + ks*512 (+ j*32)

    // ---- init ----
    for (int i = 0; i < 6; i++) {
        int idx = tid + i * NTHREADS;        // 1536 float4
        int row = idx >> 5, c4 = idx & 31;
        float4 v = __ldg((const float4*)(X0 + base + (size_t)row * H + c4 * 4));
        *(float4*)(Xs + row * XSTR + c4 * 4) = v;
    }
    if (tid < H) { sWp[tid] = __ldg(Wp + tid); sBs[tid] = __ldg(bs_ + tid); }
    if (tid < TPB) sSc[tid] = __ldg(bp);
    __syncthreads();

    float acc[3][2][4];

    // ---- attention layers ----
    for (int l = 0; l < 2; l++) {
        build_A(Xs, Ab, tid);
#pragma unroll
        for (int i = 0; i < 2; i++) {
            int j = tid + i * NTHREADS;
            int m = j >> 7, c = j & 127;
            float v;
            if      (m == 0) v = __ldg(bq_ + l * H + c);
            else if (m == 1) v = __ldg(bk_ + l * H + c);
            else if (m == 2) v = g_bvo[l][c];
            else             v = __ldg(bo_ + l * H + c);
            sB[j] = v;
        }
        __syncthreads();

        // Q, K, VO(hi+lo) passes — sync-free between them
        zero_acc(acc);
        gemm3g(AbA, aoff, fwarp + (l * 4 + 0) * 4096, acc);
        epi_qkv(acc, sB + 0, Qb, n0, g, tg);

        zero_acc(acc);
        gemm3g(AbA, aoff, fwarp + (l * 4 + 1) * 4096, acc);
        epi_qkv(acc, sB + 128, Kb, n0, g, tg);

        zero_acc(acc);
        gemm3g_b2(AbA, aoff, fwarp + (l * 4 + 2) * 4096, fwarp + (l * 4 + 3) * 4096, acc);
        epi_qkv(acc, sB + 256, Vb, n0, g, tg);
        __syncthreads();

        // attention + fused ReZero residual: Xs += beta * (P*VO + bo)
        if (tid < 96) {
            const int grp = tid / 6;
            const int rr  = tid % 6;
            const int qi  = rr >> 1;
            const int hp  = rr & 1;
            const int rb  = grp * SEQ;
            const int row = rb + qi;
            const int k0  = (qi == 0) ? 1 : 0;
            const int k1  = (qi == 2) ? 1 : 2;
            const float inv = 0.17677669529663687f;   // 1/sqrt(32)
            const float betaL = __ldg(beta + l);
            const float* bo = sB + 384;
#pragma unroll
            for (int hh = 0; hh < 2; hh++) {
                const int ho = (2 * hp + hh) * 32;
                const __nv_bfloat162* q  = (const __nv_bfloat162*)(Qb + (uint32_t)row * RB + 2u * ho);
                const __nv_bfloat162* ka = (const __nv_bfloat162*)(Kb + (uint32_t)(rb + k0) * RB + 2u * ho);
                const __nv_bfloat162* kb = (const __nv_bfloat162*)(Kb + (uint32_t)(rb + k1) * RB + 2u * ho);
                float s0 = 0.f, s1 = 0.f;
#pragma unroll
                for (int d = 0; d < 16; d++) {
                    float2 qv = __bfloat1622float2(q[d]);
                    float2 va = __bfloat1622float2(ka[d]);
                    float2 vb = __bfloat1622float2(kb[d]);
                    s0 += qv.x * va.x + qv.y * va.y;
                    s1 += qv.x * vb.x + qv.y * vb.y;
                }
                s0 *= inv; s1 *= inv;
                float mx = fmaxf(s0, s1);
                float e0 = expf(s0 - mx), e1 = expf(s1 - mx);
                float rcp = 1.0f / (e0 + e1);
                float w0 = e0 * rcp, w1 = e1 * rcp;
                const __nv_bfloat162* v0 = (const __nv_bfloat162*)(Vb + (uint32_t)(rb + k0) * RB + 2u * ho);
                const __nv_bfloat162* v1 = (const __nv_bfloat162*)(Vb + (uint32_t)(rb + k1) * RB + 2u * ho);
                float2* xp = (float2*)(Xs + row * XSTR + ho);
#pragma unroll
                for (int d = 0; d < 16; d++) {
                    float2 a = __bfloat1622float2(v0[d]);
                    float2 b = __bfloat1622float2(v1[d]);
                    float2 x = xp[d];
                    x.x += betaL * (w0 * a.x + w1 * b.x + bo[ho + 2 * d]);
                    x.y += betaL * (w0 * a.y + w1 * b.y + bo[ho + 2 * d + 1]);
                    xp[d] = x;
                }
            }
        }
        __syncthreads();
    }

    // ---- static path: relu(X0 @ Ws + bs), hi/lo split ----
#pragma unroll
    for (int i = 0; i < 12; i++) {
        int p = tid + i * NTHREADS;
        int row = p >> 6, cp = p & 63;
        float2 v = __ldg((const float2*)(X0 + base + (size_t)row * H + 2 * cp));
        __nv_bfloat16 h0 = __float2bfloat16(v.x), h1 = __float2bfloat16(v.y);
        float r0 = v.x - __bfloat162float(h0), r1 = v.y - __bfloat162float(h1);
        uint32_t off = (uint32_t)row * RB + (uint32_t)cp * 4u;
        __nv_bfloat162 hv = __halves2bfloat162(h0, h1);
        *(uint32_t*)(Kb + off) = *(uint32_t*)&hv;       // A_hi
        *(uint32_t*)(Vb + off) = bf16x2(r0, r1);        // A_lo
    }
    __syncthreads();

    zero_acc(acc);
    gemm3g_dual(KbA, VbA, aoff, fwarp + 8 * 4096, acc);   // hi*hi + lo*hi
    gemm3g(KbA, aoff, fwarp + 9 * 4096, acc);             // hi*lo

    // score epilogue
#pragma unroll
    for (int s = 0; s < 3; s++) {
        int r0 = 16 * s + g;
        float sa = 0.f, sb2 = 0.f;
#pragma unroll
        for (int j = 0; j < 2; j++) {
            int c = n0 + 8 * j + 2 * tg;
            float st, d;
            st = fmaxf(acc[s][j][0] + sBs[c], 0.f);     d = Xs[r0 * XSTR + c] - st;           sa  += d * d * sWp[c];
            st = fmaxf(acc[s][j][1] + sBs[c + 1], 0.f); d = Xs[r0 * XSTR + c + 1] - st;       sa  += d * d * sWp[c + 1];
            st = fmaxf(acc[s][j][2] + sBs[c], 0.f);     d = Xs[(r0 + 8) * XSTR + c] - st;     sb2 += d * d * sWp[c];
            st = fmaxf(acc[s][j][3] + sBs[c + 1], 0.f); d = Xs[(r0 + 8) * XSTR + c + 1] - st; sb2 += d * d * sWp[c + 1];
        }
        sa  += __shfl_xor_sync(0xffffffffu, sa, 1);
        sa  += __shfl_xor_sync(0xffffffffu, sa, 2);
        sb2 += __shfl_xor_sync(0xffffffffu, sb2, 1);
        sb2 += __shfl_xor_sync(0xffffffffu, sb2, 2);
        if (tg == 0) {
            atomicAdd(&sSc[r0], sa);
            atomicAdd(&sSc[r0 + 8], sb2);
        }
    }
    __syncthreads();

    if (tid < GPB)
        out[g0 + tid] = (sSc[tid * 3] + sSc[tid * 3 + 1] + sSc[tid * 3 + 2]) * (1.0f / 3.0f);
}

extern "C" void kernel_launch(void* const* d_in, const int* in_sizes, int n_in,
                              void* d_out, int out_size)
{
    const float* X0  = (const float*)d_in[0];
    // d_in[1] = batch (int64) — implicit: repeat(arange(G), 3)
    const float* Ws  = (const float*)d_in[2];
    const float* bs  = (const float*)d_in[3];
    const float* Wq  = (const float*)d_in[4];
    const float* bq  = (const float*)d_in[5];
    const float* Wk  = (const float*)d_in[6];
    const float* bk  = (const float*)d_in[7];
    const float* Wv  = (const float*)d_in[8];
    const float* bv  = (const float*)d_in[9];
    const float* Wo  = (const float*)d_in[10];
    const float* bo  = (const float*)d_in[11];
    const float* bet = (const float*)d_in[12];
    const float* Wp  = (const float*)d_in[13];
    const float* bp  = (const float*)d_in[14];
    float* out = (float*)d_out;

    dango_prep_vo<<<258, 128>>>(Wv, Wo, bv);
    dango_prep_pack<<<160, 256>>>(Ws, Wq, Wk);

    cudaFuncSetAttribute(dango_mma, cudaFuncAttributeMaxDynamicSharedMemorySize, SMEM_SZ);
    dango_mma<<<GROUPS / GPB, NTHREADS, SMEM_SZ>>>(
        X0, bs, bq, bk, bo, bet, Wp, bp, out);
}